// round 12
// baseline (speedup 1.0000x reference)
#include <cuda_runtime.h>

// BeliefMatchingLoss: pred [8,19,512,512] f32, target [8,512,512] int32 -> scalar f32
// Single-kernel last-block reduction; self-resetting for graph replay.
//
// loss_pix = 0.01*kl + psi(a0) - psi(a_ans)
// kl = lnG(a0) - (a0-19)*psi(a0) + sum_c g(a_c),  a_c = exp(p_c), a0 = sum a_c
// Per-class g via shift-1 (z=x+1, u=1/z, r=1/(x*z), w=x*z=fma(x,x,x)):
//   g ~= p + 1/x + z - 1.5*ln z + (5/6)u + (1/6)u^2 + u^3/90 - (C+1.5)
// Identities: 1/x = u + r (folds into poly), sum ln z = LN2*lg2(prod w) - sum p.
//
// Layout: 2 px/thread (f32x2 packed everywhere, incl. epilogue), 256-thr blocks,
// 5 CTAs/SM. smem staging pairs classes (2c,2c+1) in one 16B slot -> one LDS.128
// per 2 classes. All cp.async/LDS use [reg+imm] addressing (no per-class IADDs).

typedef unsigned long long u64;

#define HW_   (512 * 512)
#define NC_   19
#define NPIX_ (8 * HW_)
#define NTHR_ (NPIX_ / 2)
#define NBLK_ (NTHR_ / 256)

#define LN2F        0.6931471805599453f
#define LOG2EF      1.4426950408889634f
#define HALF_LN_2PI 0.91893853320467274f

__device__ double             g_sum    = 0.0;
__device__ unsigned long long g_cnt    = 0ull;
__device__ unsigned int       g_arrive = 0u;

// ---- packed f32x2 helpers (u64 = {lo,hi} fp32 pair) ----
__device__ __forceinline__ u64 pk2(float a, float b) {
    u64 r; asm("mov.b64 %0,{%1,%2};" : "=l"(r) : "f"(a), "f"(b)); return r;
}
__device__ __forceinline__ void upk2(u64 v, float& a, float& b) {
    asm("mov.b64 {%0,%1},%2;" : "=f"(a), "=f"(b) : "l"(v));
}
__device__ __forceinline__ u64 f2fma(u64 a, u64 b, u64 c) {
    u64 d; asm("fma.rn.f32x2 %0,%1,%2,%3;" : "=l"(d) : "l"(a), "l"(b), "l"(c)); return d;
}
__device__ __forceinline__ u64 f2mul(u64 a, u64 b) {
    u64 d; asm("mul.rn.f32x2 %0,%1,%2;" : "=l"(d) : "l"(a), "l"(b)); return d;
}
__device__ __forceinline__ u64 f2add(u64 a, u64 b) {
    u64 d; asm("add.rn.f32x2 %0,%1,%2;" : "=l"(d) : "l"(a), "l"(b)); return d;
}
__device__ __forceinline__ u64 f2sub(u64 a, u64 b) {
    return f2fma(b, pk2(-1.0f, -1.0f), a);
}
__device__ __forceinline__ float ex2f(float x) { float r; asm("ex2.approx.f32 %0,%1;" : "=f"(r) : "f"(x)); return r; }
__device__ __forceinline__ float lg2f_(float x){ float r; asm("lg2.approx.f32 %0,%1;" : "=f"(r) : "f"(x)); return r; }
__device__ __forceinline__ float rcpf_(float x){ float r; asm("rcp.approx.f32 %0,%1;" : "=f"(r) : "f"(x)); return r; }
__device__ __forceinline__ u64 rcp_2(u64 v) { float a, b; upk2(v, a, b); return pk2(rcpf_(a), rcpf_(b)); }
__device__ __forceinline__ u64 lg2_2(u64 v) { float a, b; upk2(v, a, b); return pk2(lg2f_(a), lg2f_(b)); }

// packed epilogue: psi+lnG at a0 (shift-2), psi at x_ans, combine both pixels
__device__ __forceinline__ u64 lane_loss(u64 a0v, u64 accP, u64 accR, u64 accU,
                                         u64 lgw, u64 xa) {
    const u64 K2p   = pk2(2.0f, 2.0f);
    const u64 K3p   = pk2(3.0f, 3.0f);
    const u64 KHp   = pk2(0.5f, 0.5f);
    const u64 K12p  = pk2(1.0f / 12.0f, 1.0f / 12.0f);
    const u64 Km120 = pk2(-1.0f / 120.0f, -1.0f / 120.0f);
    const u64 Km360 = pk2(-1.0f / 360.0f, -1.0f / 360.0f);
    const u64 KLN2  = pk2(LN2F, LN2F);

    // psi0/lg0 at a0
    u64 z0   = f2add(a0v, K2p);
    u64 P0   = f2fma(a0v, a0v, a0v);
    u64 r0   = rcp_2(f2mul(P0, z0));
    u64 S0   = f2mul(f2fma(K2p, P0, f2fma(K3p, a0v, K2p)), r0);
    u64 rz   = f2mul(P0, r0);
    u64 rz2  = f2mul(rz, rz);
    u64 lnz0 = f2mul(lg2_2(z0), KLN2);
    u64 lnP0 = f2mul(lg2_2(P0), KLN2);
    u64 cv   = f2fma(rz, KHp, f2mul(rz2, f2fma(rz2, Km120, K12p)));
    u64 tv_  = f2mul(rz, f2fma(rz2, Km360, K12p));
    u64 psi0 = f2sub(f2sub(lnz0, cv), S0);
    u64 lg0  = f2fma(f2sub(z0, KHp), lnz0, f2sub(tv_, z0));
    lg0 = f2add(f2sub(lg0, lnP0), pk2(HALF_LN_2PI, HALF_LN_2PI));

    // psia at x_ans
    u64 za   = f2add(xa, K2p);
    u64 Pa   = f2fma(xa, xa, xa);
    u64 ra   = rcp_2(f2mul(Pa, za));
    u64 Sa   = f2mul(f2fma(K2p, Pa, f2fma(K3p, xa, K2p)), ra);
    u64 rza  = f2mul(Pa, ra);
    u64 rza2 = f2mul(rza, rza);
    u64 ca   = f2fma(rza, KHp, f2mul(rza2, f2fma(rza2, Km120, K12p)));
    u64 psia = f2sub(f2sub(f2mul(lg2_2(za), KLN2), ca), Sa);

    // sum_g = 2.5*accP - 1.5*LN2*lgw + accR + accU + a0 + KADD
    const float KADDf = 19.0f * (1.0f - 1.5f - HALF_LN_2PI);
    u64 sumg = f2fma(pk2(2.5f, 2.5f), accP,
               f2fma(pk2(-1.5f * LN2F, -1.5f * LN2F), lgw, f2add(accR, accU)));
    sumg = f2add(sumg, f2add(a0v, pk2(KADDf, KADDf)));

    u64 kl = f2fma(f2sub(pk2(19.0f, 19.0f), a0v), psi0, f2add(lg0, sumg));
    return f2fma(pk2(0.01f, 0.01f), kl, f2sub(psi0, psia));
}

__global__ __launch_bounds__(256, 5) void bml_main(const float* __restrict__ pred,
                                                   const int*  __restrict__ tgt,
                                                   float*      __restrict__ out) {
    // pair-interleaved staging: pair p holds classes 2p (bytes 0-7) and 2p+1
    // (bytes 8-15) at [p*4096 + tid*16]; pair 9 holds class 18 in its low 8B.
    __shared__ __align__(16) char smq[10 * 4096];

    unsigned tid = threadIdx.x;
    int tix = blockIdx.x * 256 + (int)tid;
    int pix = tix * 2;
    int b   = pix >> 18;
    int hw  = pix & (HW_ - 1);
    const float* pp = pred + (size_t)b * NC_ * HW_ + hw;

    unsigned sbase;
    asm("{ .reg .u64 t; cvta.to.shared.u64 t, %1; cvt.u32.u64 %0, t; }"
        : "=r"(sbase) : "l"(smq));
    unsigned stid = sbase + tid * 16u;

    // ---- stage classes 0..18; all addressing via [reg+imm] ----
#define CPA(c) asm volatile( \
        "cp.async.ca.shared.global [%0+%2], [%1+%3], 8;" \
        :: "r"(stid), "l"(pp), \
           "n"(((c) >> 1) * 4096 + ((c) & 1) * 8), \
           "n"((long long)(c) * HW_ * 4) : "memory")
#define CG() asm volatile("cp.async.commit_group;" ::: "memory")
    CPA(0);  CPA(1);  CPA(2);  CPA(3);  CG();
    CPA(4);  CPA(5);  CPA(6);  CPA(7);  CG();
    CPA(8);  CPA(9);  CPA(10); CPA(11); CG();
    CPA(12); CPA(13); CPA(14); CPA(15); CG();
    CPA(16); CPA(17); CPA(18);          CG();
#undef CPA
#undef CG

    int2 tv  = *reinterpret_cast<const int2*>(tgt + pix);
    bool ig0 = (tv.x == 255), ig1 = (tv.y == 255);
    int  ta0 = ig0 ? 0 : tv.x;
    int  ta1 = ig1 ? 0 : tv.y;

    const u64 KL2E = pk2(LOG2EF, LOG2EF);
    const u64 Ca   = pk2(11.0f / 6.0f, 11.0f / 6.0f);   // 5/6 + 1 (1/x fold)
    const u64 Cb   = pk2(0.17333333f, 0.17333333f);     // 1/6 + 1/150 (u^3 fold)

    u64 accU = pk2(0.0f, 0.0f);   // sum u*(Ca + Cb*u)
    u64 accR = accU;              // sum r  (r = 1/(x z))
    u64 accP = accU;              // sum p  (= sum ln x, exact)
    u64 a0v  = accU;              // sum x
    u64 lgw  = accU;              // sum lg2(W_group), W = prod x*z

#define WAITG(n) asm volatile("cp.async.wait_group %0;" :: "n"(n) : "memory")

    // one LDS.128 per class pair
#define LDSP(pvA, pvB, p) asm volatile("ld.shared.v2.b64 {%0,%1},[%2+%3];" \
        : "=l"(pvA), "=l"(pvB) : "r"(stid), "n"((p) * 4096))

    // stage1: accumulate p, exp, w = x(x+1) = fma(x,x,x)
#define S1(pv, xx, ww) do {                                                   \
        accP = f2add(accP, pv);                                               \
        u64 e = f2mul(pv, KL2E);                                              \
        float el, eh; upk2(e, el, eh);                                        \
        (xx) = pk2(ex2f(el), ex2f(eh));                                       \
        (ww) = f2fma((xx), (xx), (xx));                                       \
    } while (0)

#define S2(xx, rr) do {                                                       \
        u64 u_ = f2mul((xx), (rr));                                           \
        u64 q  = f2fma(u_, Cb, Ca);                                           \
        accU   = f2fma(u_, q, accU);                                          \
        accR   = f2add(accR, (rr));                                           \
        a0v    = f2add(a0v, (xx));                                            \
    } while (0)

#define QUAD(k, wg) do {                                                      \
        WAITG(wg);                                                            \
        u64 p0, p1, p2, p3;                                                   \
        LDSP(p0, p1, 2 * (k));                                                \
        LDSP(p2, p3, 2 * (k) + 1);                                            \
        u64 x0, w0, x1, w1, x2, w2, x3, w3;                                   \
        S1(p0, x0, w0); S1(p1, x1, w1); S1(p2, x2, w2); S1(p3, x3, w3);       \
        u64 Wab = f2mul(w0, w1);                                              \
        u64 Wcd = f2mul(w2, w3);                                              \
        u64 Wq  = f2mul(Wab, Wcd);                                            \
        lgw = f2add(lgw, lg2_2(Wq));                                          \
        u64 rr  = rcp_2(Wq);                                                  \
        u64 rab = f2mul(rr, Wcd);                                             \
        u64 rcd = f2mul(rr, Wab);                                             \
        S2(x0, f2mul(rab, w1));                                               \
        S2(x1, f2mul(rab, w0));                                               \
        S2(x2, f2mul(rcd, w3));                                               \
        S2(x3, f2mul(rcd, w2));                                               \
    } while (0)

    QUAD(0, 4); QUAD(1, 3); QUAD(2, 2); QUAD(3, 1);
    { // tail: classes 16,17 (pair 8) + class 18 (pair 9 low half)
        WAITG(0);
        u64 p0, p1, p2;
        LDSP(p0, p1, 8);
        asm volatile("ld.shared.b64 %0,[%1+%2];"
                     : "=l"(p2) : "r"(stid), "n"(9 * 4096));
        u64 x0, w0, x1, w1, x2, w2;
        S1(p0, x0, w0); S1(p1, x1, w1); S1(p2, x2, w2);
        u64 Wab = f2mul(w0, w1);
        u64 Wq  = f2mul(Wab, w2);
        lgw = f2add(lgw, lg2_2(Wq));
        u64 rr  = rcp_2(Wq);
        u64 rab = f2mul(rr, w2);
        S2(x0, f2mul(rab, w1));
        S2(x1, f2mul(rab, w0));
        S2(x2, f2mul(rr, Wab));
    }
#undef QUAD
#undef S1
#undef S2
#undef LDSP
#undef WAITG

    // answer-class logits from smem: class c at [(c>>1)*4096 + (c&1)*8 (+4 hi px)]
    float pa0, pa1;
    asm volatile("ld.shared.f32 %0,[%1];" : "=f"(pa0)
                 : "r"(stid + (unsigned)((ta0 >> 1) * 4096 + (ta0 & 1) * 8)));
    asm volatile("ld.shared.f32 %0,[%1];" : "=f"(pa1)
                 : "r"(stid + (unsigned)((ta1 >> 1) * 4096 + (ta1 & 1) * 8 + 4)));

    u64 xa = pk2(ex2f(pa0 * LOG2EF), ex2f(pa1 * LOG2EF));
    u64 lossp = lane_loss(a0v, accP, accR, accU, lgw, xa);

    float loss_lo, loss_hi;
    upk2(lossp, loss_lo, loss_hi);
    if (ig0) loss_lo = 0.0f;
    if (ig1) loss_hi = 0.0f;
    float loss = loss_lo + loss_hi;

    unsigned m0 = __ballot_sync(0xffffffffu, ig0);
    unsigned m1 = __ballot_sync(0xffffffffu, ig1);
    int valid_w = 64 - __popc(m0) - __popc(m1);

#pragma unroll
    for (int o = 16; o; o >>= 1)
        loss += __shfl_down_sync(0xffffffffu, loss, o);

    __shared__ float s_l[8];
    __shared__ int   s_v[8];
    int wid = threadIdx.x >> 5;
    int lid = threadIdx.x & 31;
    if (lid == 0) { s_l[wid] = loss; s_v[wid] = valid_w; }
    __syncthreads();

    if (threadIdx.x == 0) {
        float L = 0.0f;
        int   V = 0;
#pragma unroll
        for (int w = 0; w < 8; ++w) { L += s_l[w]; V += s_v[w]; }
        atomicAdd(&g_sum, (double)L);
        atomicAdd(&g_cnt, (unsigned long long)V);
        __threadfence();
        unsigned int n = atomicAdd(&g_arrive, 1u);
        if (n == (unsigned int)(NBLK_ - 1)) {
            __threadfence();
            double s = *((volatile double*)&g_sum);
            unsigned long long c = *((volatile unsigned long long*)&g_cnt);
            out[0] = (float)(s / (double)c);
            g_sum    = 0.0;
            g_cnt    = 0ull;
            g_arrive = 0u;
        }
    }
}

extern "C" void kernel_launch(void* const* d_in, const int* in_sizes, int n_in,
                              void* d_out, int out_size) {
    const float* pred = (const float*)d_in[0];
    const int*   tgt  = (const int*)d_in[1];
    float*       out  = (float*)d_out;

    bml_main<<<NBLK_, 256>>>(pred, tgt, out);
}

// round 13
// speedup vs baseline: 1.0463x; 1.0463x over previous
#include <cuda_runtime.h>

// BeliefMatchingLoss: pred [8,19,512,512] f32, target [8,512,512] int32 -> scalar f32
// PERSISTENT kernel: 740 CTAs (148 SM x 5), each loops over tiles of 512 px,
// with cross-tile cp.async software pipelining: after consuming chunk q of
// tile t, issue chunk q of tile t+1 (same smem slots) and commit. Outstanding
// groups are always 5 -> uniform wait_group(4); after tile 0 no warp waits on
// cold DRAM. Last-block reduction; self-resetting for graph replay.
//
// Math (identical to the 36.7us kernel, rel_err 7.2e-5):
// loss_pix = 0.01*kl + psi(a0) - psi(a_ans)
// per-class g via shift-1 (z=x+1, u=1/z, r=1/(x*z), w=x*z):
//   g ~= p + 1/x + z - 1.5*ln z + (5/6)u + (1/6)u^2 + u^3/90 - (C+1.5)
// Identities: 1/x = u + r (folds into poly), sum ln z = LN2*lg2(prod w) - sum p.

typedef unsigned long long u64;

#define HW_    (512 * 512)
#define NC_    19
#define NPIX_  (8 * HW_)
#define TPB_   256
#define NTILES (NPIX_ / (2 * TPB_))   // 4096 tiles of 512 px
#define GRID_  740                    // 148 SMs x 5 CTAs

#define LN2F        0.6931471805599453f
#define LOG2EF      1.4426950408889634f
#define HALF_LN_2PI 0.91893853320467274f

__device__ double             g_sum    = 0.0;
__device__ unsigned long long g_cnt    = 0ull;
__device__ unsigned int       g_arrive = 0u;

// ---- packed f32x2 helpers (u64 = {lo,hi} fp32 pair) ----
__device__ __forceinline__ u64 pk2(float a, float b) {
    u64 r; asm("mov.b64 %0,{%1,%2};" : "=l"(r) : "f"(a), "f"(b)); return r;
}
__device__ __forceinline__ void upk2(u64 v, float& a, float& b) {
    asm("mov.b64 {%0,%1},%2;" : "=f"(a), "=f"(b) : "l"(v));
}
__device__ __forceinline__ u64 f2fma(u64 a, u64 b, u64 c) {
    u64 d; asm("fma.rn.f32x2 %0,%1,%2,%3;" : "=l"(d) : "l"(a), "l"(b), "l"(c)); return d;
}
__device__ __forceinline__ u64 f2mul(u64 a, u64 b) {
    u64 d; asm("mul.rn.f32x2 %0,%1,%2;" : "=l"(d) : "l"(a), "l"(b)); return d;
}
__device__ __forceinline__ u64 f2add(u64 a, u64 b) {
    u64 d; asm("add.rn.f32x2 %0,%1,%2;" : "=l"(d) : "l"(a), "l"(b)); return d;
}
__device__ __forceinline__ u64 f2sub(u64 a, u64 b) {
    return f2fma(b, pk2(-1.0f, -1.0f), a);
}
__device__ __forceinline__ float ex2f(float x) { float r; asm("ex2.approx.f32 %0,%1;" : "=f"(r) : "f"(x)); return r; }
__device__ __forceinline__ float lg2f_(float x){ float r; asm("lg2.approx.f32 %0,%1;" : "=f"(r) : "f"(x)); return r; }
__device__ __forceinline__ float rcpf_(float x){ float r; asm("rcp.approx.f32 %0,%1;" : "=f"(r) : "f"(x)); return r; }
__device__ __forceinline__ u64 rcp_2(u64 v) { float a, b; upk2(v, a, b); return pk2(rcpf_(a), rcpf_(b)); }
__device__ __forceinline__ u64 lg2_2(u64 v) { float a, b; upk2(v, a, b); return pk2(lg2f_(a), lg2f_(b)); }

// packed epilogue: psi+lnG at a0 (shift-2), psi at x_ans, combine both pixels
__device__ __forceinline__ u64 lane_loss(u64 a0v, u64 accP, u64 accR, u64 accU,
                                         u64 lgw, u64 xa) {
    const u64 K2p   = pk2(2.0f, 2.0f);
    const u64 K3p   = pk2(3.0f, 3.0f);
    const u64 KHp   = pk2(0.5f, 0.5f);
    const u64 K12p  = pk2(1.0f / 12.0f, 1.0f / 12.0f);
    const u64 Km120 = pk2(-1.0f / 120.0f, -1.0f / 120.0f);
    const u64 Km360 = pk2(-1.0f / 360.0f, -1.0f / 360.0f);
    const u64 KLN2  = pk2(LN2F, LN2F);

    u64 z0   = f2add(a0v, K2p);
    u64 P0   = f2fma(a0v, a0v, a0v);
    u64 r0   = rcp_2(f2mul(P0, z0));
    u64 S0   = f2mul(f2fma(K2p, P0, f2fma(K3p, a0v, K2p)), r0);
    u64 rz   = f2mul(P0, r0);
    u64 rz2  = f2mul(rz, rz);
    u64 lnz0 = f2mul(lg2_2(z0), KLN2);
    u64 lnP0 = f2mul(lg2_2(P0), KLN2);
    u64 cv   = f2fma(rz, KHp, f2mul(rz2, f2fma(rz2, Km120, K12p)));
    u64 tv_  = f2mul(rz, f2fma(rz2, Km360, K12p));
    u64 psi0 = f2sub(f2sub(lnz0, cv), S0);
    u64 lg0  = f2fma(f2sub(z0, KHp), lnz0, f2sub(tv_, z0));
    lg0 = f2add(f2sub(lg0, lnP0), pk2(HALF_LN_2PI, HALF_LN_2PI));

    u64 za   = f2add(xa, K2p);
    u64 Pa   = f2fma(xa, xa, xa);
    u64 ra   = rcp_2(f2mul(Pa, za));
    u64 Sa   = f2mul(f2fma(K2p, Pa, f2fma(K3p, xa, K2p)), ra);
    u64 rza  = f2mul(Pa, ra);
    u64 rza2 = f2mul(rza, rza);
    u64 ca   = f2fma(rza, KHp, f2mul(rza2, f2fma(rza2, Km120, K12p)));
    u64 psia = f2sub(f2sub(f2mul(lg2_2(za), KLN2), ca), Sa);

    const float KADDf = 19.0f * (1.0f - 1.5f - HALF_LN_2PI);
    u64 sumg = f2fma(pk2(2.5f, 2.5f), accP,
               f2fma(pk2(-1.5f * LN2F, -1.5f * LN2F), lgw, f2add(accR, accU)));
    sumg = f2add(sumg, f2add(a0v, pk2(KADDf, KADDf)));

    u64 kl = f2fma(f2sub(pk2(19.0f, 19.0f), a0v), psi0, f2add(lg0, sumg));
    return f2fma(pk2(0.01f, 0.01f), kl, f2sub(psi0, psia));
}

__global__ __launch_bounds__(TPB_, 5) void bml_main(const float* __restrict__ pred,
                                                    const int*  __restrict__ tgt,
                                                    float*      __restrict__ out) {
    __shared__ u64 smq[NC_ * TPB_];   // 38912 B, slot [c*256 + tid]

    unsigned tid = threadIdx.x;
    unsigned sbase;
    asm("{ .reg .u64 t; cvta.to.shared.u64 t, %1; cvt.u32.u64 %0, t; }"
        : "=r"(sbase) : "l"(smq));
    unsigned stid = sbase + tid * 8u;

    // per-tile pred pointer for pixel pair (tile*512 + tid*2)
#define TILE_PP(t_) (pred + (size_t)(((t_) * 512 + (int)tid * 2) >> 18) * NC_ * HW_ \
                          + (((t_) * 512 + (int)tid * 2) & (HW_ - 1)))

    // issue one chunk (4 or 3 classes) of staged loads at base pointer q
#define CPA(q, c) asm volatile( \
        "cp.async.ca.shared.global [%0+%2], [%1+%3], 8;" \
        :: "r"(stid), "l"(q), "n"((c) * 2048), \
           "n"((long long)(c) * HW_ * 4) : "memory")
#define CG() asm volatile("cp.async.commit_group;" ::: "memory")
#define ISSUE_CHUNK(q, k) do {                                                \
        if ((k) == 0) { CPA(q, 0);  CPA(q, 1);  CPA(q, 2);  CPA(q, 3);  }     \
        if ((k) == 1) { CPA(q, 4);  CPA(q, 5);  CPA(q, 6);  CPA(q, 7);  }     \
        if ((k) == 2) { CPA(q, 8);  CPA(q, 9);  CPA(q, 10); CPA(q, 11); }     \
        if ((k) == 3) { CPA(q, 12); CPA(q, 13); CPA(q, 14); CPA(q, 15); }     \
        if ((k) == 4) { CPA(q, 16); CPA(q, 17); CPA(q, 18); }                 \
    } while (0)

    int t = blockIdx.x;
    const float* pp = TILE_PP(t);

    // prologue: stage tile t completely (5 commit groups)
    ISSUE_CHUNK(pp, 0); CG();
    ISSUE_CHUNK(pp, 1); CG();
    ISSUE_CHUNK(pp, 2); CG();
    ISSUE_CHUNK(pp, 3); CG();
    ISSUE_CHUNK(pp, 4); CG();

    const u64 KL2E = pk2(LOG2EF, LOG2EF);
    const u64 Ca   = pk2(11.0f / 6.0f, 11.0f / 6.0f);   // 5/6 + 1 (1/x fold)
    const u64 Cb   = pk2(0.17333333f, 0.17333333f);     // 1/6 + 1/150 (u^3 fold)

    float lossAcc = 0.0f;
    int   validAcc = 0;

#define WAITG4() asm volatile("cp.async.wait_group 4;" ::: "memory")

#define S1(c, xx, ww) do {                                                    \
        u64 pv;                                                               \
        asm volatile("ld.shared.b64 %0,[%1+%2];"                              \
                     : "=l"(pv) : "r"(stid), "n"((c) * 2048));                \
        accP = f2add(accP, pv);                                               \
        u64 e = f2mul(pv, KL2E);                                              \
        float el, eh; upk2(e, el, eh);                                        \
        (xx) = pk2(ex2f(el), ex2f(eh));                                       \
        (ww) = f2fma((xx), (xx), (xx));                                       \
    } while (0)

#define S2(xx, rr) do {                                                       \
        u64 u_ = f2mul((xx), (rr));                                           \
        u64 q  = f2fma(u_, Cb, Ca);                                           \
        accU   = f2fma(u_, q, accU);                                          \
        accR   = f2add(accR, (rr));                                           \
        a0v    = f2add(a0v, (xx));                                            \
    } while (0)

    while (true) {
        int  tn       = t + GRID_;
        bool has_next = tn < NTILES;
        const float* ppn = has_next ? TILE_PP(tn) : pp;

        // targets + answer gathers for THIS tile (global; consumed at epilogue)
        int pix = t * 512 + (int)tid * 2;
        int2 tvv = *reinterpret_cast<const int2*>(tgt + pix);
        bool ig0 = (tvv.x == 255), ig1 = (tvv.y == 255);
        int  ta0 = ig0 ? 0 : tvv.x;
        int  ta1 = ig1 ? 0 : tvv.y;
        float pa0 = __ldg(pp + (size_t)ta0 * HW_);
        float pa1 = __ldg(pp + (size_t)ta1 * HW_ + 1);

        u64 accU = pk2(0.0f, 0.0f);
        u64 accR = accU, accP = accU, a0v = accU, lgw = accU;

#define CHUNK4(c0, k) do {                                                    \
        WAITG4();                                                             \
        u64 x0, w0, x1, w1, x2, w2, x3, w3;                                   \
        S1((c0) + 0, x0, w0); S1((c0) + 1, x1, w1);                           \
        S1((c0) + 2, x2, w2); S1((c0) + 3, x3, w3);                           \
        if (has_next) ISSUE_CHUNK(ppn, k);                                    \
        CG();                                                                 \
        u64 Wab = f2mul(w0, w1);                                              \
        u64 Wcd = f2mul(w2, w3);                                              \
        u64 Wq  = f2mul(Wab, Wcd);                                            \
        lgw = f2add(lgw, lg2_2(Wq));                                          \
        u64 rr  = rcp_2(Wq);                                                  \
        u64 rab = f2mul(rr, Wcd);                                             \
        u64 rcd = f2mul(rr, Wab);                                             \
        S2(x0, f2mul(rab, w1));                                               \
        S2(x1, f2mul(rab, w0));                                               \
        S2(x2, f2mul(rcd, w3));                                               \
        S2(x3, f2mul(rcd, w2));                                               \
    } while (0)

        CHUNK4(0, 0);
        CHUNK4(4, 1);
        CHUNK4(8, 2);
        CHUNK4(12, 3);
        { // tail chunk: classes 16,17,18
            WAITG4();
            u64 x0, w0, x1, w1, x2, w2;
            S1(16, x0, w0); S1(17, x1, w1); S1(18, x2, w2);
            if (has_next) ISSUE_CHUNK(ppn, 4);
            CG();
            u64 Wab = f2mul(w0, w1);
            u64 Wq  = f2mul(Wab, w2);
            lgw = f2add(lgw, lg2_2(Wq));
            u64 rr  = rcp_2(Wq);
            u64 rab = f2mul(rr, w2);
            S2(x0, f2mul(rab, w1));
            S2(x1, f2mul(rab, w0));
            S2(x2, f2mul(rr, Wab));
        }
#undef CHUNK4

        // epilogue for this tile
        u64 xa = pk2(ex2f(pa0 * LOG2EF), ex2f(pa1 * LOG2EF));
        u64 lossp = lane_loss(a0v, accP, accR, accU, lgw, xa);
        float l0, l1;
        upk2(lossp, l0, l1);
        if (ig0) l0 = 0.0f;
        if (ig1) l1 = 0.0f;
        lossAcc += l0 + l1;
        unsigned m0 = __ballot_sync(0xffffffffu, ig0);
        unsigned m1 = __ballot_sync(0xffffffffu, ig1);
        validAcc += 64 - __popc(m0) - __popc(m1);

        if (!has_next) break;
        t  = tn;
        pp = ppn;
    }
#undef S1
#undef S2
#undef ISSUE_CHUNK
#undef CPA
#undef CG
#undef WAITG4
#undef TILE_PP

    // block reduction (validAcc uniform per warp; take lane 0's)
#pragma unroll
    for (int o = 16; o; o >>= 1)
        lossAcc += __shfl_down_sync(0xffffffffu, lossAcc, o);

    __shared__ float s_l[8];
    __shared__ int   s_v[8];
    int wid = threadIdx.x >> 5;
    int lid = threadIdx.x & 31;
    if (lid == 0) { s_l[wid] = lossAcc; s_v[wid] = validAcc; }
    __syncthreads();

    if (threadIdx.x == 0) {
        float L = 0.0f;
        int   V = 0;
#pragma unroll
        for (int w = 0; w < 8; ++w) { L += s_l[w]; V += s_v[w]; }
        atomicAdd(&g_sum, (double)L);
        atomicAdd(&g_cnt, (unsigned long long)V);
        __threadfence();
        unsigned int n = atomicAdd(&g_arrive, 1u);
        if (n == (unsigned int)(GRID_ - 1)) {
            __threadfence();
            double s = *((volatile double*)&g_sum);
            unsigned long long c = *((volatile unsigned long long*)&g_cnt);
            out[0] = (float)(s / (double)c);
            g_sum    = 0.0;
            g_cnt    = 0ull;
            g_arrive = 0u;
        }
    }
}

extern "C" void kernel_launch(void* const* d_in, const int* in_sizes, int n_in,
                              void* d_out, int out_size) {
    const float* pred = (const float*)d_in[0];
    const int*   tgt  = (const int*)d_in[1];
    float*       out  = (float*)d_out;

    bml_main<<<GRID_, TPB_>>>(pred, tgt, out);
}